// round 3
// baseline (speedup 1.0000x reference)
#include <cuda_runtime.h>
#include <cuda_fp16.h>
#include <cuda_bf16.h>

// Problem constants.
#define EMB 256
#define MAX_NODES 100000
#define MAX_EDGES 3200000
#define SCAN_BLK 1024
#define MAX_SCAN_BLOCKS 128

// -------- device scratch (no allocations allowed) --------
__device__ __half d_Ph[MAX_NODES * EMB];  // P = emb @ W in fp16 (51.2 MB)
__device__ int   d_rowptr[MAX_NODES + 1];
__device__ int   d_cursor[MAX_NODES + 1];
__device__ int   d_scol[MAX_EDGES];
__device__ float d_sval[MAX_EDGES];
__device__ int   d_blocksums[MAX_SCAN_BLOCKS];
__device__ int   d_blockoffs[MAX_SCAN_BLOCKS];

// ---------------- K0: zero counts ----------------
__global__ void zero_counts_kernel(int n) {
    int i = blockIdx.x * blockDim.x + threadIdx.x;
    if (i <= n) d_cursor[i] = 0;
}

// ---------------- K1: histogram of rows ----------------
__global__ void hist_kernel(const int* __restrict__ rows, int E) {
    int e = blockIdx.x * blockDim.x + threadIdx.x;
    if (e < E) atomicAdd(&d_cursor[rows[e]], 1);
}

// ---------------- scan helpers ----------------
__device__ __forceinline__ int warp_incl_scan(int v, int lane) {
    #pragma unroll
    for (int off = 1; off < 32; off <<= 1) {
        int x = __shfl_up_sync(0xffffffffu, v, off);
        if (lane >= off) v += x;
    }
    return v;
}

__global__ __launch_bounds__(SCAN_BLK) void scan_block_kernel(int n) {
    __shared__ int wsum[SCAN_BLK / 32];
    const int t = threadIdx.x;
    const int lane = t & 31;
    const int warp = t >> 5;
    const int i = blockIdx.x * SCAN_BLK + t;

    int v = (i < n) ? d_cursor[i] : 0;
    int incl = warp_incl_scan(v, lane);
    if (lane == 31) wsum[warp] = incl;
    __syncthreads();
    if (warp == 0) {
        int s = (lane < SCAN_BLK / 32) ? wsum[lane] : 0;
        s = warp_incl_scan(s, lane);
        if (lane < SCAN_BLK / 32) wsum[lane] = s;
    }
    __syncthreads();
    int base = (warp > 0) ? wsum[warp - 1] : 0;
    if (i < n) d_rowptr[i] = base + incl - v;
    if (t == SCAN_BLK - 1) d_blocksums[blockIdx.x] = base + incl;
}

__global__ __launch_bounds__(128) void scan_sums_kernel(int nblocks, int n) {
    __shared__ int wsum[4];
    const int t = threadIdx.x;
    const int lane = t & 31;
    const int warp = t >> 5;
    int v = (t < nblocks) ? d_blocksums[t] : 0;
    int incl = warp_incl_scan(v, lane);
    if (lane == 31) wsum[warp] = incl;
    __syncthreads();
    if (warp == 0) {
        int s = (lane < 4) ? wsum[lane] : 0;
        s = warp_incl_scan(s, lane);
        if (lane < 4) wsum[lane] = s;
    }
    __syncthreads();
    int base = (warp > 0) ? wsum[warp - 1] : 0;
    if (t < nblocks) d_blockoffs[t] = base + incl - v;
    if (t == 127) d_rowptr[n] = wsum[3];
}

__global__ __launch_bounds__(SCAN_BLK) void scan_add_kernel(int n) {
    const int i = blockIdx.x * SCAN_BLK + threadIdx.x;
    if (i < n) {
        int r = d_rowptr[i] + d_blockoffs[blockIdx.x];
        d_rowptr[i] = r;
        d_cursor[i] = r;
    }
}

// ---------------- K3: scatter edges into CSR order ----------------
__global__ void scatter_kernel(const int* __restrict__ rows,
                               const int* __restrict__ cols,
                               const float* __restrict__ vals, int E) {
    int e = blockIdx.x * blockDim.x + threadIdx.x;
    if (e < E) {
        int r = rows[e];
        int p = atomicAdd(&d_cursor[r], 1);
        d_scol[p] = cols[e];
        d_sval[p] = vals[e];
    }
}

// ---------------- K4: P = emb @ W, fp32 compute, fp16 store ----------------
// BM=128, BN=64, BK=32. 256 threads, 8x4 microtile.
#define BM 128
#define BN 64
#define BK 32
__global__ __launch_bounds__(256) void gemm_kernel(const float* __restrict__ A,
                                                   const float* __restrict__ B,
                                                   int M) {
    __shared__ float sA[BK][BM + 8];   // transposed, padded (136 floats/row)
    __shared__ float sB[BK][BN];
    const int tid = threadIdx.x;
    const int tx = tid & 15;        // 0..15 -> N (4 cols each)
    const int ty = tid >> 4;        // 0..15 -> M (8 rows each)
    const int row0 = blockIdx.x * BM;
    const int col0 = blockIdx.y * BN;

    float acc[8][4];
    #pragma unroll
    for (int m = 0; m < 8; m++)
        #pragma unroll
        for (int n = 0; n < 4; n++) acc[m][n] = 0.f;

    for (int k0 = 0; k0 < EMB; k0 += BK) {
        // A tile: BM x BK floats = 1024 float4; 4 float4 per thread.
        #pragma unroll
        for (int i = 0; i < 4; i++) {
            int f4 = tid + i * 256;          // float4 index in tile
            int r = f4 >> 3;                 // row (8 float4 per row)
            int c4 = f4 & 7;                 // which float4 within row
            float4 a = {0.f, 0.f, 0.f, 0.f};
            if (row0 + r < M)
                a = *reinterpret_cast<const float4*>(&A[(long)(row0 + r) * EMB + k0 + c4 * 4]);
            sA[c4 * 4 + 0][r] = a.x;
            sA[c4 * 4 + 1][r] = a.y;
            sA[c4 * 4 + 2][r] = a.z;
            sA[c4 * 4 + 3][r] = a.w;
        }
        // B tile: BK x BN = 512 float4; 2 per thread.
        #pragma unroll
        for (int i = 0; i < 2; i++) {
            int f4 = tid + i * 256;
            int r = f4 >> 4;                 // 16 float4 per row
            int c4 = f4 & 15;
            *reinterpret_cast<float4*>(&sB[r][c4 * 4]) =
                *reinterpret_cast<const float4*>(&B[(k0 + r) * EMB + col0 + c4 * 4]);
        }
        __syncthreads();
        #pragma unroll
        for (int k = 0; k < BK; k++) {
            float4 a0 = *reinterpret_cast<const float4*>(&sA[k][ty * 8]);
            float4 a1 = *reinterpret_cast<const float4*>(&sA[k][ty * 8 + 4]);
            float4 b4 = *reinterpret_cast<const float4*>(&sB[k][tx * 4]);
            float a[8] = {a0.x, a0.y, a0.z, a0.w, a1.x, a1.y, a1.z, a1.w};
            float b[4] = {b4.x, b4.y, b4.z, b4.w};
            #pragma unroll
            for (int m = 0; m < 8; m++)
                #pragma unroll
                for (int n = 0; n < 4; n++)
                    acc[m][n] = fmaf(a[m], b[n], acc[m][n]);
        }
        __syncthreads();
    }
    #pragma unroll
    for (int m = 0; m < 8; m++) {
        int r = row0 + ty * 8 + m;
        if (r < M) {
            __half2 h01 = __floats2half2_rn(acc[m][0], acc[m][1]);
            __half2 h23 = __floats2half2_rn(acc[m][2], acc[m][3]);
            __half2* dst = reinterpret_cast<__half2*>(&d_Ph[(long)r * EMB + col0 + tx * 4]);
            dst[0] = h01;
            dst[1] = h23;
        }
    }
}

// ---------------- K5: SpMM in fp16-P space + ReLU -> fp32 out ----------------
// One warp per row; each lane owns 8 columns (one uint4 = 8 halfs per gather).
__global__ __launch_bounds__(256) void spmm_relu_kernel(float* __restrict__ out,
                                                        int nrows) {
    const int warp = blockIdx.x * (blockDim.x >> 5) + (threadIdx.x >> 5);
    if (warp >= nrows) return;
    const int lane = threadIdx.x & 31;
    const int s = d_rowptr[warp];
    const int e = d_rowptr[warp + 1];

    float acc[8];
    #pragma unroll
    for (int i = 0; i < 8; i++) acc[i] = 0.f;

    const uint4* __restrict__ Pv = reinterpret_cast<const uint4*>(d_Ph); // 32 uint4/row

    for (int base = s; base < e; base += 32) {
        int idx = base + lane;
        int c = 0;
        float v = 0.f;
        if (idx < e) { c = d_scol[idx]; v = d_sval[idx]; }
        int cnt = e - base; if (cnt > 32) cnt = 32;
        #pragma unroll 2
        for (int j = 0; j < cnt; j++) {
            int   cj = __shfl_sync(0xffffffffu, c, j);
            float vj = __shfl_sync(0xffffffffu, v, j);
            uint4 q = Pv[(long)cj * 32 + lane];
            float2 f0 = __half22float2(*reinterpret_cast<__half2*>(&q.x));
            float2 f1 = __half22float2(*reinterpret_cast<__half2*>(&q.y));
            float2 f2 = __half22float2(*reinterpret_cast<__half2*>(&q.z));
            float2 f3 = __half22float2(*reinterpret_cast<__half2*>(&q.w));
            acc[0] = fmaf(vj, f0.x, acc[0]);
            acc[1] = fmaf(vj, f0.y, acc[1]);
            acc[2] = fmaf(vj, f1.x, acc[2]);
            acc[3] = fmaf(vj, f1.y, acc[3]);
            acc[4] = fmaf(vj, f2.x, acc[4]);
            acc[5] = fmaf(vj, f2.y, acc[5]);
            acc[6] = fmaf(vj, f3.x, acc[6]);
            acc[7] = fmaf(vj, f3.y, acc[7]);
        }
    }
    float4 o0 = {fmaxf(acc[0], 0.f), fmaxf(acc[1], 0.f), fmaxf(acc[2], 0.f), fmaxf(acc[3], 0.f)};
    float4 o1 = {fmaxf(acc[4], 0.f), fmaxf(acc[5], 0.f), fmaxf(acc[6], 0.f), fmaxf(acc[7], 0.f)};
    float4* outv = reinterpret_cast<float4*>(out);   // 64 float4 per row
    outv[(long)warp * 64 + lane * 2]     = o0;
    outv[(long)warp * 64 + lane * 2 + 1] = o1;
}

// ---------------- launch ----------------
extern "C" void kernel_launch(void* const* d_in, const int* in_sizes, int n_in,
                              void* d_out, int out_size) {
    const float* emb  = (const float*)d_in[0];
    const int*   rows = (const int*)  d_in[1];
    const int*   cols = (const int*)  d_in[2];
    const float* vals = (const float*)d_in[3];
    const float* W    = (const float*)d_in[4];
    float* out = (float*)d_out;

    const int N = in_sizes[0] / EMB;   // 100000
    const int E = in_sizes[1];         // 3200000

    const int nsb = (N + SCAN_BLK - 1) / SCAN_BLK;

    // Launch order chosen so gemm_kernel is my launch #3 (ncu captures it).
    zero_counts_kernel<<<(N + 256) / 256, 256>>>(N);           // 0
    hist_kernel<<<(E + 511) / 512, 512>>>(rows, E);            // 1
    scan_block_kernel<<<nsb, SCAN_BLK>>>(N);                   // 2
    dim3 ggrid((N + BM - 1) / BM, EMB / BN);
    gemm_kernel<<<ggrid, 256>>>(emb, W, N);                    // 3  <- profiled
    scan_sums_kernel<<<1, 128>>>(nsb, N);                      // 4
    scan_add_kernel<<<nsb, SCAN_BLK>>>(N);                     // 5
    scatter_kernel<<<(E + 511) / 512, 512>>>(rows, cols, vals, E); // 6
    int warps_per_block = 256 / 32;
    int sgrid = (N + warps_per_block - 1) / warps_per_block;
    spmm_relu_kernel<<<sgrid, 256>>>(out, N);                  // 7
}

// round 4
// speedup vs baseline: 2.6080x; 2.6080x over previous
#include <cuda_runtime.h>
#include <cuda_fp16.h>
#include <cuda_bf16.h>
#include <mma.h>

using namespace nvcuda;

// Problem constants.
#define EMB 256
#define MAX_NODES 100000
#define MAX_EDGES 3200000
#define SCAN_BLK 1024
#define MAX_SCAN_BLOCKS 128

// -------- device scratch (no allocations allowed) --------
__device__ __half d_Ph[MAX_NODES * EMB];  // P = emb @ W in fp16 (51.2 MB)
__device__ int   d_rowptr[MAX_NODES + 1];
__device__ int   d_cursor[MAX_NODES + 1];
__device__ int2  d_edge[MAX_EDGES];       // (col, bitcast(val))
__device__ int   d_blocksums[MAX_SCAN_BLOCKS];
__device__ int   d_blockoffs[MAX_SCAN_BLOCKS];

// ---------------- K0: zero counts ----------------
__global__ void zero_counts_kernel(int n) {
    int i = blockIdx.x * blockDim.x + threadIdx.x;
    if (i <= n) d_cursor[i] = 0;
}

// ---------------- K1: histogram of rows ----------------
__global__ void hist_kernel(const int* __restrict__ rows, int E) {
    int e = blockIdx.x * blockDim.x + threadIdx.x;
    if (e < E) atomicAdd(&d_cursor[rows[e]], 1);
}

// ---------------- scan helpers ----------------
__device__ __forceinline__ int warp_incl_scan(int v, int lane) {
    #pragma unroll
    for (int off = 1; off < 32; off <<= 1) {
        int x = __shfl_up_sync(0xffffffffu, v, off);
        if (lane >= off) v += x;
    }
    return v;
}

__global__ __launch_bounds__(SCAN_BLK) void scan_block_kernel(int n) {
    __shared__ int wsum[SCAN_BLK / 32];
    const int t = threadIdx.x;
    const int lane = t & 31;
    const int warp = t >> 5;
    const int i = blockIdx.x * SCAN_BLK + t;

    int v = (i < n) ? d_cursor[i] : 0;
    int incl = warp_incl_scan(v, lane);
    if (lane == 31) wsum[warp] = incl;
    __syncthreads();
    if (warp == 0) {
        int s = (lane < SCAN_BLK / 32) ? wsum[lane] : 0;
        s = warp_incl_scan(s, lane);
        if (lane < SCAN_BLK / 32) wsum[lane] = s;
    }
    __syncthreads();
    int base = (warp > 0) ? wsum[warp - 1] : 0;
    if (i < n) d_rowptr[i] = base + incl - v;
    if (t == SCAN_BLK - 1) d_blocksums[blockIdx.x] = base + incl;
}

__global__ __launch_bounds__(128) void scan_sums_kernel(int nblocks, int n) {
    __shared__ int wsum[4];
    const int t = threadIdx.x;
    const int lane = t & 31;
    const int warp = t >> 5;
    int v = (t < nblocks) ? d_blocksums[t] : 0;
    int incl = warp_incl_scan(v, lane);
    if (lane == 31) wsum[warp] = incl;
    __syncthreads();
    if (warp == 0) {
        int s = (lane < 4) ? wsum[lane] : 0;
        s = warp_incl_scan(s, lane);
        if (lane < 4) wsum[lane] = s;
    }
    __syncthreads();
    int base = (warp > 0) ? wsum[warp - 1] : 0;
    if (t < nblocks) d_blockoffs[t] = base + incl - v;
    if (t == 127) d_rowptr[n] = wsum[3];
}

__global__ __launch_bounds__(SCAN_BLK) void scan_add_kernel(int n) {
    const int i = blockIdx.x * SCAN_BLK + threadIdx.x;
    if (i < n) {
        int r = d_rowptr[i] + d_blockoffs[blockIdx.x];
        d_rowptr[i] = r;
        d_cursor[i] = r;
    }
}

// ---------------- K3: scatter edges into CSR order ----------------
__global__ void scatter_kernel(const int* __restrict__ rows,
                               const int* __restrict__ cols,
                               const float* __restrict__ vals, int E) {
    int e = blockIdx.x * blockDim.x + threadIdx.x;
    if (e < E) {
        int r = rows[e];
        int p = atomicAdd(&d_cursor[r], 1);
        d_edge[p] = make_int2(cols[e], __float_as_int(vals[e]));
    }
}

// ---------------- K4: P = emb @ W via HMMA (wmma), fp16 store ----------------
// BLOCK_M=128, BLOCK_N=64, 512 threads (16 warps).
// Warp grid: 4 (M) x 4 (N); warp tile 32x16 = 2 m16n16k16 fragments.
#define GBM 128
#define GBN 64
#define GBK 32
#define A_LD 40   // 32 + 8 pad (halfs)
#define B_LD 72   // 64 + 8 pad (halfs)
#define O_LD 72   // floats

__global__ __launch_bounds__(512) void gemm_kernel(const float* __restrict__ A,
                                                   const float* __restrict__ B,
                                                   int M) {
    __shared__ alignas(16) unsigned char smem_raw[GBM * O_LD * 4]; // 36864B, max of phases
    __half (*sA)[A_LD] = reinterpret_cast<__half(*)[A_LD]>(smem_raw);                  // 128x40 halfs = 10240B
    __half (*sB)[B_LD] = reinterpret_cast<__half(*)[B_LD]>(smem_raw + GBM * A_LD * 2); // 32x72 halfs  = 4608B
    float  (*sO)[O_LD] = reinterpret_cast<float(*)[O_LD]>(smem_raw);                   // 128x72 floats

    const int tid = threadIdx.x;
    const int warp = tid >> 5;
    const int warp_m = warp & 3;   // 0..3 -> m offset 32*warp_m
    const int warp_n = warp >> 2;  // 0..3 -> n offset 16*warp_n
    const int row0 = blockIdx.x * GBM;
    const int col0 = blockIdx.y * GBN;

    wmma::fragment<wmma::accumulator, 16, 16, 16, float> acc[2];
    wmma::fill_fragment(acc[0], 0.f);
    wmma::fill_fragment(acc[1], 0.f);

    for (int k0 = 0; k0 < EMB; k0 += GBK) {
        // A tile: 128 rows x 32 cols fp32 -> fp16. 1024 float4, 2 per thread.
        #pragma unroll
        for (int i = 0; i < 2; i++) {
            int f4 = tid + i * 512;
            int r = f4 >> 3;           // 8 float4 per row
            int c4 = f4 & 7;
            float4 a = {0.f, 0.f, 0.f, 0.f};
            if (row0 + r < M)
                a = *reinterpret_cast<const float4*>(&A[(long)(row0 + r) * EMB + k0 + c4 * 4]);
            __half2* dst = reinterpret_cast<__half2*>(&sA[r][c4 * 4]);
            dst[0] = __floats2half2_rn(a.x, a.y);
            dst[1] = __floats2half2_rn(a.z, a.w);
        }
        // B tile: 32 rows x 64 cols fp32 -> fp16. 512 float4, 1 per thread.
        {
            int r = tid >> 4;          // 16 float4 per row
            int c4 = tid & 15;
            float4 b = *reinterpret_cast<const float4*>(&B[(k0 + r) * EMB + col0 + c4 * 4]);
            __half2* dst = reinterpret_cast<__half2*>(&sB[r][c4 * 4]);
            dst[0] = __floats2half2_rn(b.x, b.y);
            dst[1] = __floats2half2_rn(b.z, b.w);
        }
        __syncthreads();

        #pragma unroll
        for (int kk = 0; kk < GBK; kk += 16) {
            wmma::fragment<wmma::matrix_a, 16, 16, 16, __half, wmma::row_major> af;
            wmma::fragment<wmma::matrix_b, 16, 16, 16, __half, wmma::row_major> bf;
            wmma::load_matrix_sync(bf, &sB[kk][warp_n * 16], B_LD);
            #pragma unroll
            for (int i = 0; i < 2; i++) {
                wmma::load_matrix_sync(af, &sA[warp_m * 32 + i * 16][kk], A_LD);
                wmma::mma_sync(acc[i], af, bf, acc[i]);
            }
        }
        __syncthreads();
    }

    // Epilogue: acc -> smem fp32 -> global fp16
    #pragma unroll
    for (int i = 0; i < 2; i++)
        wmma::store_matrix_sync(&sO[warp_m * 32 + i * 16][warp_n * 16], acc[i],
                                O_LD, wmma::mem_row_major);
    __syncthreads();

    // 128x64 floats -> half, 2048 groups of 4, 4 per thread.
    #pragma unroll
    for (int i = 0; i < 4; i++) {
        int g = tid + i * 512;
        int r = g >> 4;            // 16 groups per row
        int c4 = g & 15;
        if (row0 + r < M) {
            float4 v = *reinterpret_cast<const float4*>(&sO[r][c4 * 4]);
            __half2 h01 = __floats2half2_rn(v.x, v.y);
            __half2 h23 = __floats2half2_rn(v.z, v.w);
            __half2* dst = reinterpret_cast<__half2*>(&d_Ph[(long)(row0 + r) * EMB + col0 + c4 * 4]);
            dst[0] = h01;
            dst[1] = h23;
        }
    }
}

// ---------------- K5: SpMM in fp16-P space + ReLU -> fp32 out ----------------
__global__ __launch_bounds__(256) void spmm_relu_kernel(float* __restrict__ out,
                                                        int nrows) {
    const int warp = blockIdx.x * (blockDim.x >> 5) + (threadIdx.x >> 5);
    if (warp >= nrows) return;
    const int lane = threadIdx.x & 31;
    const int s = d_rowptr[warp];
    const int e = d_rowptr[warp + 1];

    float acc[8];
    #pragma unroll
    for (int i = 0; i < 8; i++) acc[i] = 0.f;

    const uint4* __restrict__ Pv = reinterpret_cast<const uint4*>(d_Ph);

    for (int base = s; base < e; base += 32) {
        int idx = base + lane;
        int c = 0;
        float v = 0.f;
        if (idx < e) {
            int2 ev = d_edge[idx];
            c = ev.x;
            v = __int_as_float(ev.y);
        }
        int cnt = e - base; if (cnt > 32) cnt = 32;
        #pragma unroll 2
        for (int j = 0; j < cnt; j++) {
            int   cj = __shfl_sync(0xffffffffu, c, j);
            float vj = __shfl_sync(0xffffffffu, v, j);
            uint4 q = Pv[(long)cj * 32 + lane];
            float2 f0 = __half22float2(*reinterpret_cast<__half2*>(&q.x));
            float2 f1 = __half22float2(*reinterpret_cast<__half2*>(&q.y));
            float2 f2 = __half22float2(*reinterpret_cast<__half2*>(&q.z));
            float2 f3 = __half22float2(*reinterpret_cast<__half2*>(&q.w));
            acc[0] = fmaf(vj, f0.x, acc[0]);
            acc[1] = fmaf(vj, f0.y, acc[1]);
            acc[2] = fmaf(vj, f1.x, acc[2]);
            acc[3] = fmaf(vj, f1.y, acc[3]);
            acc[4] = fmaf(vj, f2.x, acc[4]);
            acc[5] = fmaf(vj, f2.y, acc[5]);
            acc[6] = fmaf(vj, f3.x, acc[6]);
            acc[7] = fmaf(vj, f3.y, acc[7]);
        }
    }
    float4 o0 = {fmaxf(acc[0], 0.f), fmaxf(acc[1], 0.f), fmaxf(acc[2], 0.f), fmaxf(acc[3], 0.f)};
    float4 o1 = {fmaxf(acc[4], 0.f), fmaxf(acc[5], 0.f), fmaxf(acc[6], 0.f), fmaxf(acc[7], 0.f)};
    float4* outv = reinterpret_cast<float4*>(out);
    outv[(long)warp * 64 + lane * 2]     = o0;
    outv[(long)warp * 64 + lane * 2 + 1] = o1;
}

// ---------------- launch ----------------
extern "C" void kernel_launch(void* const* d_in, const int* in_sizes, int n_in,
                              void* d_out, int out_size) {
    const float* emb  = (const float*)d_in[0];
    const int*   rows = (const int*)  d_in[1];
    const int*   cols = (const int*)  d_in[2];
    const float* vals = (const float*)d_in[3];
    const float* W    = (const float*)d_in[4];
    float* out = (float*)d_out;

    const int N = in_sizes[0] / EMB;   // 100000
    const int E = in_sizes[1];         // 3200000

    const int nsb = (N + SCAN_BLK - 1) / SCAN_BLK;

    // Same launch order as round 3 so ncu (launch idx 3) profiles gemm_kernel.
    zero_counts_kernel<<<(N + 256) / 256, 256>>>(N);               // 0
    hist_kernel<<<(E + 511) / 512, 512>>>(rows, E);                // 1
    scan_block_kernel<<<nsb, SCAN_BLK>>>(N);                       // 2
    dim3 ggrid((N + GBM - 1) / GBM, EMB / GBN);
    gemm_kernel<<<ggrid, 512>>>(emb, W, N);                        // 3  <- profiled
    scan_sums_kernel<<<1, 128>>>(nsb, N);                          // 4
    scan_add_kernel<<<nsb, SCAN_BLK>>>(N);                         // 5
    scatter_kernel<<<(E + 511) / 512, 512>>>(rows, cols, vals, E); // 6
    int warps_per_block = 256 / 32;
    int sgrid = (N + warps_per_block - 1) / warps_per_block;
    spmm_relu_kernel<<<sgrid, 256>>>(out, N);                      // 7
}

// round 6
// speedup vs baseline: 2.7673x; 1.0611x over previous
#include <cuda_runtime.h>
#include <cuda_fp16.h>
#include <cuda_bf16.h>
#include <mma.h>

using namespace nvcuda;

// Problem constants.
#define EMB 256
#define MAX_NODES 100000
#define MAX_EDGES 3200000
#define SCAN_BLK 1024
#define MAX_SCAN_BLOCKS 128

// -------- device scratch (no allocations allowed) --------
__device__ __half d_Ph[MAX_NODES * EMB];  // P = emb @ W in fp16 (51.2 MB)
__device__ int   d_rowptr[MAX_NODES + 1];
__device__ int   d_cursor[MAX_NODES + 1];
__device__ int2  d_edge[MAX_EDGES];       // (col, bitcast(val))
__device__ int   d_blocksums[MAX_SCAN_BLOCKS];
__device__ int   d_blockoffs[MAX_SCAN_BLOCKS];

// ---------------- K0: zero counts ----------------
__global__ void zero_counts_kernel(int n) {
    int i = blockIdx.x * blockDim.x + threadIdx.x;
    if (i <= n) d_cursor[i] = 0;
}

// ---------------- K1: histogram of rows ----------------
__global__ void hist_kernel(const int* __restrict__ rows, int E) {
    int e = blockIdx.x * blockDim.x + threadIdx.x;
    if (e < E) atomicAdd(&d_cursor[rows[e]], 1);
}

// ---------------- scan helpers ----------------
__device__ __forceinline__ int warp_incl_scan(int v, int lane) {
    #pragma unroll
    for (int off = 1; off < 32; off <<= 1) {
        int x = __shfl_up_sync(0xffffffffu, v, off);
        if (lane >= off) v += x;
    }
    return v;
}

__global__ __launch_bounds__(SCAN_BLK) void scan_block_kernel(int n) {
    __shared__ int wsum[SCAN_BLK / 32];
    const int t = threadIdx.x;
    const int lane = t & 31;
    const int warp = t >> 5;
    const int i = blockIdx.x * SCAN_BLK + t;

    int v = (i < n) ? d_cursor[i] : 0;
    int incl = warp_incl_scan(v, lane);
    if (lane == 31) wsum[warp] = incl;
    __syncthreads();
    if (warp == 0) {
        int s = (lane < SCAN_BLK / 32) ? wsum[lane] : 0;
        s = warp_incl_scan(s, lane);
        if (lane < SCAN_BLK / 32) wsum[lane] = s;
    }
    __syncthreads();
    int base = (warp > 0) ? wsum[warp - 1] : 0;
    if (i < n) d_rowptr[i] = base + incl - v;
    if (t == SCAN_BLK - 1) d_blocksums[blockIdx.x] = base + incl;
}

__global__ __launch_bounds__(128) void scan_sums_kernel(int nblocks, int n) {
    __shared__ int wsum[4];
    const int t = threadIdx.x;
    const int lane = t & 31;
    const int warp = t >> 5;
    int v = (t < nblocks) ? d_blocksums[t] : 0;
    int incl = warp_incl_scan(v, lane);
    if (lane == 31) wsum[warp] = incl;
    __syncthreads();
    if (warp == 0) {
        int s = (lane < 4) ? wsum[lane] : 0;
        s = warp_incl_scan(s, lane);
        if (lane < 4) wsum[lane] = s;
    }
    __syncthreads();
    int base = (warp > 0) ? wsum[warp - 1] : 0;
    if (t < nblocks) d_blockoffs[t] = base + incl - v;
    if (t == 127) d_rowptr[n] = wsum[3];
}

__global__ __launch_bounds__(SCAN_BLK) void scan_add_kernel(int n) {
    const int i = blockIdx.x * SCAN_BLK + threadIdx.x;
    if (i < n) {
        int r = d_rowptr[i] + d_blockoffs[blockIdx.x];
        d_rowptr[i] = r;
        d_cursor[i] = r;
    }
}

// ---------------- K3: scatter edges into CSR order ----------------
__global__ void scatter_kernel(const int* __restrict__ rows,
                               const int* __restrict__ cols,
                               const float* __restrict__ vals, int E) {
    int e = blockIdx.x * blockDim.x + threadIdx.x;
    if (e < E) {
        int r = rows[e];
        int p = atomicAdd(&d_cursor[r], 1);
        d_edge[p] = make_int2(cols[e], __float_as_int(vals[e]));
    }
}

// ---------------- K4: P = emb @ W via HMMA, full-width output block ----------
// GBM=64 rows per CTA, GBN=256 (full OUT) -> A read exactly once from DRAM.
// 512 threads = 16 warps as 2(M) x 8(N); warp tile 32x32 = 2x2 m16n16k16 frags.
#define GBM 64
#define GBK 32
#define A_LD 40    // 32 + 8 pad (halfs)
#define B_LD 264   // 256 + 8 pad (halfs)
#define W_LD 20    // 16 + 4 pad (floats): 80B row stride keeps float4 alignment

__global__ __launch_bounds__(512, 2) void gemm_kernel(const float* __restrict__ A,
                                                      const float* __restrict__ B,
                                                      int M) {
    __shared__ __half sA[GBM][A_LD];          // 5120 B
    __shared__ __half sB[GBK][B_LD];          // 16896 B
    __shared__ alignas(16) float sW[16][16][W_LD];  // 20480 B per-warp bounce

    const int tid = threadIdx.x;
    const int warp = tid >> 5;
    const int lane = tid & 31;
    const int warp_m = warp >> 3;   // 0..1 -> m offset 32*warp_m
    const int warp_n = warp & 7;    // 0..7 -> n offset 32*warp_n
    const int row0 = blockIdx.x * GBM;

    wmma::fragment<wmma::accumulator, 16, 16, 16, float> acc[2][2];
    #pragma unroll
    for (int i = 0; i < 2; i++)
        #pragma unroll
        for (int j = 0; j < 2; j++) wmma::fill_fragment(acc[i][j], 0.f);

    for (int k0 = 0; k0 < EMB; k0 += GBK) {
        // A tile: 64 x 32 fp32 -> fp16. 512 float4, 1 per thread.
        {
            int r = tid >> 3;          // 8 float4 per row
            int c4 = tid & 7;
            float4 a = {0.f, 0.f, 0.f, 0.f};
            if (row0 + r < M)
                a = *reinterpret_cast<const float4*>(&A[(long)(row0 + r) * EMB + k0 + c4 * 4]);
            __half2* dst = reinterpret_cast<__half2*>(&sA[r][c4 * 4]);
            dst[0] = __floats2half2_rn(a.x, a.y);
            dst[1] = __floats2half2_rn(a.z, a.w);
        }
        // B tile: 32 x 256 fp32 -> fp16. 2048 float4, 4 per thread.
        #pragma unroll
        for (int i = 0; i < 4; i++) {
            int f4 = tid + i * 512;
            int r = f4 >> 6;           // 64 float4 per row
            int c4 = f4 & 63;
            float4 b = *reinterpret_cast<const float4*>(&B[(k0 + r) * EMB + c4 * 4]);
            __half2* dst = reinterpret_cast<__half2*>(&sB[r][c4 * 4]);
            dst[0] = __floats2half2_rn(b.x, b.y);
            dst[1] = __floats2half2_rn(b.z, b.w);
        }
        __syncthreads();

        #pragma unroll
        for (int kk = 0; kk < GBK; kk += 16) {
            #pragma unroll
            for (int j = 0; j < 2; j++) {
                wmma::fragment<wmma::matrix_b, 16, 16, 16, __half, wmma::row_major> bf;
                wmma::load_matrix_sync(bf, &sB[kk][warp_n * 32 + j * 16], B_LD);
                #pragma unroll
                for (int i = 0; i < 2; i++) {
                    wmma::fragment<wmma::matrix_a, 16, 16, 16, __half, wmma::row_major> af;
                    wmma::load_matrix_sync(af, &sA[warp_m * 32 + i * 16][kk], A_LD);
                    wmma::mma_sync(acc[i][j], af, bf, acc[i][j]);
                }
            }
        }
        __syncthreads();
    }

    // Per-warp epilogue: bounce each 16x16 frag through smem, convert to fp16.
    const int er = lane >> 1;              // 0..15 row in frag
    const int ec0 = (lane & 1) * 8;        // 0 or 8
    #pragma unroll
    for (int i = 0; i < 2; i++) {
        #pragma unroll
        for (int j = 0; j < 2; j++) {
            wmma::store_matrix_sync(&sW[warp][0][0], acc[i][j], W_LD, wmma::mem_row_major);
            __syncwarp();
            int g_r = row0 + warp_m * 32 + i * 16 + er;
            if (g_r < M) {
                float4 v0 = *reinterpret_cast<const float4*>(&sW[warp][er][ec0]);
                float4 v1 = *reinterpret_cast<const float4*>(&sW[warp][er][ec0 + 4]);
                __half2 h[4] = {__floats2half2_rn(v0.x, v0.y), __floats2half2_rn(v0.z, v0.w),
                                __floats2half2_rn(v1.x, v1.y), __floats2half2_rn(v1.z, v1.w)};
                *reinterpret_cast<uint4*>(&d_Ph[(long)g_r * EMB + warp_n * 32 + j * 16 + ec0]) =
                    *reinterpret_cast<uint4*>(h);
            }
            __syncwarp();
        }
    }
}

// ---------------- K5: SpMM in fp16-P space + ReLU -> fp32 out ----------------
__global__ __launch_bounds__(256) void spmm_relu_kernel(float* __restrict__ out,
                                                        int nrows) {
    const int warp = blockIdx.x * (blockDim.x >> 5) + (threadIdx.x >> 5);
    if (warp >= nrows) return;
    const int lane = threadIdx.x & 31;
    const int s = d_rowptr[warp];
    const int e = d_rowptr[warp + 1];

    float acc[8];
    #pragma unroll
    for (int i = 0; i < 8; i++) acc[i] = 0.f;

    const uint4* __restrict__ Pv = reinterpret_cast<const uint4*>(d_Ph);

    for (int base = s; base < e; base += 32) {
        int idx = base + lane;
        int c = 0;
        float v = 0.f;
        if (idx < e) {
            int2 ev = d_edge[idx];
            c = ev.x;
            v = __int_as_float(ev.y);
        }
        int cnt = e - base; if (cnt > 32) cnt = 32;
        #pragma unroll 2
        for (int j = 0; j < cnt; j++) {
            int   cj = __shfl_sync(0xffffffffu, c, j);
            float vj = __shfl_sync(0xffffffffu, v, j);
            uint4 q = Pv[(long)cj * 32 + lane];
            float2 f0 = __half22float2(*reinterpret_cast<__half2*>(&q.x));
            float2 f1 = __half22float2(*reinterpret_cast<__half2*>(&q.y));
            float2 f2 = __half22float2(*reinterpret_cast<__half2*>(&q.z));
            float2 f3 = __half22float2(*reinterpret_cast<__half2*>(&q.w));
            acc[0] = fmaf(vj, f0.x, acc[0]);
            acc[1] = fmaf(vj, f0.y, acc[1]);
            acc[2] = fmaf(vj, f1.x, acc[2]);
            acc[3] = fmaf(vj, f1.y, acc[3]);
            acc[4] = fmaf(vj, f2.x, acc[4]);
            acc[5] = fmaf(vj, f2.y, acc[5]);
            acc[6] = fmaf(vj, f3.x, acc[6]);
            acc[7] = fmaf(vj, f3.y, acc[7]);
        }
    }
    float4 o0 = {fmaxf(acc[0], 0.f), fmaxf(acc[1], 0.f), fmaxf(acc[2], 0.f), fmaxf(acc[3], 0.f)};
    float4 o1 = {fmaxf(acc[4], 0.f), fmaxf(acc[5], 0.f), fmaxf(acc[6], 0.f), fmaxf(acc[7], 0.f)};
    float4* outv = reinterpret_cast<float4*>(out);
    outv[(long)warp * 64 + lane * 2]     = o0;
    outv[(long)warp * 64 + lane * 2 + 1] = o1;
}

// ---------------- launch ----------------
extern "C" void kernel_launch(void* const* d_in, const int* in_sizes, int n_in,
                              void* d_out, int out_size) {
    const float* emb  = (const float*)d_in[0];
    const int*   rows = (const int*)  d_in[1];
    const int*   cols = (const int*)  d_in[2];
    const float* vals = (const float*)d_in[3];
    const float* W    = (const float*)d_in[4];
    float* out = (float*)d_out;

    const int N = in_sizes[0] / EMB;   // 100000
    const int E = in_sizes[1];         // 3200000

    const int nsb = (N + SCAN_BLK - 1) / SCAN_BLK;

    // gemm_kernel stays launch idx 3 so ncu profiles it.
    zero_counts_kernel<<<(N + 256) / 256, 256>>>(N);               // 0
    hist_kernel<<<(E + 511) / 512, 512>>>(rows, E);                // 1
    scan_block_kernel<<<nsb, SCAN_BLK>>>(N);                       // 2
    gemm_kernel<<<(N + GBM - 1) / GBM, 512>>>(emb, W, N);          // 3  <- profiled
    scan_sums_kernel<<<1, 128>>>(nsb, N);                          // 4
    scan_add_kernel<<<nsb, SCAN_BLK>>>(N);                         // 5
    scatter_kernel<<<(E + 511) / 512, 512>>>(rows, cols, vals, E); // 6
    int warps_per_block = 256 / 32;
    int sgrid = (N + warps_per_block - 1) / warps_per_block;
    spmm_relu_kernel<<<sgrid, 256>>>(out, N);                      // 7
}

// round 7
// speedup vs baseline: 2.8406x; 1.0265x over previous
#include <cuda_runtime.h>
#include <cuda_fp16.h>
#include <cuda_bf16.h>
#include <mma.h>

using namespace nvcuda;

// Problem constants.
#define EMB 256
#define MAX_NODES 100000
#define MAX_EDGES 3200000
#define SCAN_BLK 1024
#define MAX_SCAN_BLOCKS 128

// -------- device scratch (no allocations allowed) --------
__device__ __half d_Ph[MAX_NODES * EMB];  // P = emb @ W in fp16 (51.2 MB)
__device__ int   d_rowptr[MAX_NODES + 1];
__device__ int   d_cursor[MAX_NODES + 1];
__device__ int2  d_edge[MAX_EDGES];       // (col, bitcast(val))
__device__ int   d_blocksums[MAX_SCAN_BLOCKS];
__device__ int   d_blockoffs[MAX_SCAN_BLOCKS];

// ---------------- K0: zero counts ----------------
__global__ void zero_counts_kernel(int n) {
    int i = blockIdx.x * blockDim.x + threadIdx.x;
    if (i <= n) d_cursor[i] = 0;
}

// ---------------- K1: histogram of rows ----------------
__global__ void hist_kernel(const int* __restrict__ rows, int E) {
    int e = blockIdx.x * blockDim.x + threadIdx.x;
    if (e < E) atomicAdd(&d_cursor[rows[e]], 1);
}

// ---------------- scan helpers ----------------
__device__ __forceinline__ int warp_incl_scan(int v, int lane) {
    #pragma unroll
    for (int off = 1; off < 32; off <<= 1) {
        int x = __shfl_up_sync(0xffffffffu, v, off);
        if (lane >= off) v += x;
    }
    return v;
}

__global__ __launch_bounds__(SCAN_BLK) void scan_block_kernel(int n) {
    __shared__ int wsum[SCAN_BLK / 32];
    const int t = threadIdx.x;
    const int lane = t & 31;
    const int warp = t >> 5;
    const int i = blockIdx.x * SCAN_BLK + t;

    int v = (i < n) ? d_cursor[i] : 0;
    int incl = warp_incl_scan(v, lane);
    if (lane == 31) wsum[warp] = incl;
    __syncthreads();
    if (warp == 0) {
        int s = (lane < SCAN_BLK / 32) ? wsum[lane] : 0;
        s = warp_incl_scan(s, lane);
        if (lane < SCAN_BLK / 32) wsum[lane] = s;
    }
    __syncthreads();
    int base = (warp > 0) ? wsum[warp - 1] : 0;
    if (i < n) d_rowptr[i] = base + incl - v;
    if (t == SCAN_BLK - 1) d_blocksums[blockIdx.x] = base + incl;
}

__global__ __launch_bounds__(128) void scan_sums_kernel(int nblocks, int n) {
    __shared__ int wsum[4];
    const int t = threadIdx.x;
    const int lane = t & 31;
    const int warp = t >> 5;
    int v = (t < nblocks) ? d_blocksums[t] : 0;
    int incl = warp_incl_scan(v, lane);
    if (lane == 31) wsum[warp] = incl;
    __syncthreads();
    if (warp == 0) {
        int s = (lane < 4) ? wsum[lane] : 0;
        s = warp_incl_scan(s, lane);
        if (lane < 4) wsum[lane] = s;
    }
    __syncthreads();
    int base = (warp > 0) ? wsum[warp - 1] : 0;
    if (t < nblocks) d_blockoffs[t] = base + incl - v;
    if (t == 127) d_rowptr[n] = wsum[3];
}

__global__ __launch_bounds__(SCAN_BLK) void scan_add_kernel(int n) {
    const int i = blockIdx.x * SCAN_BLK + threadIdx.x;
    if (i < n) {
        int r = d_rowptr[i] + d_blockoffs[blockIdx.x];
        d_rowptr[i] = r;
        d_cursor[i] = r;
    }
}

// ---------------- K3: scatter edges into CSR order ----------------
__global__ void scatter_kernel(const int* __restrict__ rows,
                               const int* __restrict__ cols,
                               const float* __restrict__ vals, int E) {
    int e = blockIdx.x * blockDim.x + threadIdx.x;
    if (e < E) {
        int r = rows[e];
        int p = atomicAdd(&d_cursor[r], 1);
        d_edge[p] = make_int2(cols[e], __float_as_int(vals[e]));
    }
}

// ---------------- K4: persistent HMMA GEMM, W resident in smem ------------
// Grid = 152 CTAs x 1024 threads. Each CTA: convert W (256x256) to fp16 smem
// once, then loop over 128-row blocks (stride gridDim.x) with a double-
// buffered A pipeline (1 float4 load/thread/iter overlapped with MMAs).
#define GBM 128
#define GBK 32
#define A_LD 40    // 32 + 8 pad (halfs), 80B row stride (16B aligned)
#define B_LD 264   // 256 + 8 pad (halfs), 528B row stride (16B aligned)
#define E_LD 20    // 16 + 4 pad (floats), 80B row stride (16B aligned)

#define SM_W_BYTES  (256 * B_LD * 2)            // 135168
#define SM_A_BYTES  (GBM * A_LD * 2)            // 10240 per buffer
#define SM_E_OFF    (SM_W_BYTES + 2 * SM_A_BYTES)   // 155648 (16B aligned)
#define SM_TOTAL    (SM_E_OFF + 32 * 16 * E_LD * 4) // 196608

extern __shared__ char gemm_smem[];

__global__ __launch_bounds__(1024, 1) void gemm_kernel(const float* __restrict__ A,
                                                       const float* __restrict__ W,
                                                       int M, int nblk) {
    __half (*sWm)[B_LD] = reinterpret_cast<__half(*)[B_LD]>(gemm_smem);
    __half (*sA0)[A_LD] = reinterpret_cast<__half(*)[A_LD]>(gemm_smem + SM_W_BYTES);
    __half (*sA1)[A_LD] = reinterpret_cast<__half(*)[A_LD]>(gemm_smem + SM_W_BYTES + SM_A_BYTES);
    float  (*sE)[16][E_LD] = reinterpret_cast<float(*)[16][E_LD]>(gemm_smem + SM_E_OFF);

    const int tid = threadIdx.x;
    const int warp = tid >> 5;
    const int lane = tid & 31;
    const int warp_m = warp >> 3;   // 0..3 -> m offset 32*warp_m
    const int warp_n = warp & 7;    // 0..7 -> n offset 32*warp_n

    // Convert full W (256x256 fp32) into fp16 smem. 16384 float4, 16/thread.
    #pragma unroll
    for (int i = 0; i < 16; i++) {
        int g = tid + i * 1024;
        int r = g >> 6;            // 64 float4 per row
        int c4 = g & 63;
        float4 b = *reinterpret_cast<const float4*>(&W[r * EMB + c4 * 4]);
        __half2* dst = reinterpret_cast<__half2*>(&sWm[r][c4 * 4]);
        dst[0] = __floats2half2_rn(b.x, b.y);
        dst[1] = __floats2half2_rn(b.z, b.w);
    }

    const int a_r = tid >> 3;      // 0..127 (row in A tile)
    const int a_c4 = tid & 7;      // 0..7   (float4 within 32-wide K chunk)
    const int er = lane >> 1;      // epilogue row in 16x16 frag
    const int ec0 = (lane & 1) * 8;

    for (int blk = blockIdx.x; blk < nblk; blk += gridDim.x) {
        const int row0 = blk * GBM;

        // Stage A tile k0=0 into sA0.
        {
            float4 a = {0.f, 0.f, 0.f, 0.f};
            if (row0 + a_r < M)
                a = *reinterpret_cast<const float4*>(&A[(long)(row0 + a_r) * EMB + a_c4 * 4]);
            __half2* dst = reinterpret_cast<__half2*>(&sA0[a_r][a_c4 * 4]);
            dst[0] = __floats2half2_rn(a.x, a.y);
            dst[1] = __floats2half2_rn(a.z, a.w);
        }

        wmma::fragment<wmma::accumulator, 16, 16, 16, float> acc[2][2];
        #pragma unroll
        for (int i = 0; i < 2; i++)
            #pragma unroll
            for (int j = 0; j < 2; j++) wmma::fill_fragment(acc[i][j], 0.f);

        __syncthreads();   // sA0 ready (also fences previous block's MMAs)

        #pragma unroll
        for (int k0 = 0; k0 < EMB / GBK; k0++) {
            // Prefetch next A tile into registers.
            float4 an = {0.f, 0.f, 0.f, 0.f};
            const bool pf = (k0 < EMB / GBK - 1);
            if (pf && row0 + a_r < M)
                an = *reinterpret_cast<const float4*>(
                    &A[(long)(row0 + a_r) * EMB + (k0 + 1) * GBK + a_c4 * 4]);

            __half (*cur)[A_LD] = (k0 & 1) ? sA1 : sA0;
            __half (*nxt)[A_LD] = (k0 & 1) ? sA0 : sA1;

            // MMAs on current buffer against resident W.
            #pragma unroll
            for (int kk = 0; kk < GBK; kk += 16) {
                #pragma unroll
                for (int j = 0; j < 2; j++) {
                    wmma::fragment<wmma::matrix_b, 16, 16, 16, __half, wmma::row_major> bf;
                    wmma::load_matrix_sync(bf, &sWm[k0 * GBK + kk][warp_n * 32 + j * 16], B_LD);
                    #pragma unroll
                    for (int i = 0; i < 2; i++) {
                        wmma::fragment<wmma::matrix_a, 16, 16, 16, __half, wmma::row_major> af;
                        wmma::load_matrix_sync(af, &cur[warp_m * 32 + i * 16][kk], A_LD);
                        wmma::mma_sync(acc[i][j], af, bf, acc[i][j]);
                    }
                }
            }

            // Store prefetched tile into the other buffer.
            if (pf) {
                __half2* dst = reinterpret_cast<__half2*>(&nxt[a_r][a_c4 * 4]);
                dst[0] = __floats2half2_rn(an.x, an.y);
                dst[1] = __floats2half2_rn(an.z, an.w);
            }
            __syncthreads();
        }

        // Per-warp epilogue: bounce each 16x16 frag through private smem slab.
        #pragma unroll
        for (int i = 0; i < 2; i++) {
            #pragma unroll
            for (int j = 0; j < 2; j++) {
                wmma::store_matrix_sync(&sE[warp][0][0], acc[i][j], E_LD, wmma::mem_row_major);
                __syncwarp();
                int g_r = row0 + warp_m * 32 + i * 16 + er;
                if (g_r < M) {
                    float4 v0 = *reinterpret_cast<const float4*>(&sE[warp][er][ec0]);
                    float4 v1 = *reinterpret_cast<const float4*>(&sE[warp][er][ec0 + 4]);
                    __half2 h[4] = {__floats2half2_rn(v0.x, v0.y), __floats2half2_rn(v0.z, v0.w),
                                    __floats2half2_rn(v1.x, v1.y), __floats2half2_rn(v1.z, v1.w)};
                    *reinterpret_cast<uint4*>(&d_Ph[(long)g_r * EMB + warp_n * 32 + j * 16 + ec0]) =
                        *reinterpret_cast<uint4*>(h);
                }
                __syncwarp();
            }
        }
        // No block-wide sync needed: next iteration's pre-MMA __syncthreads
        // orders sA reuse, and sE slabs are per-warp private.
    }
}

// ---------------- K5: SpMM in fp16-P space + ReLU -> fp32 out ----------------
__global__ __launch_bounds__(256) void spmm_relu_kernel(float* __restrict__ out,
                                                        int nrows) {
    const int warp = blockIdx.x * (blockDim.x >> 5) + (threadIdx.x >> 5);
    if (warp >= nrows) return;
    const int lane = threadIdx.x & 31;
    const int s = d_rowptr[warp];
    const int e = d_rowptr[warp + 1];

    float acc[8];
    #pragma unroll
    for (int i = 0; i < 8; i++) acc[i] = 0.f;

    const uint4* __restrict__ Pv = reinterpret_cast<const uint4*>(d_Ph);

    for (int base = s; base < e; base += 32) {
        int idx = base + lane;
        int c = 0;
        float v = 0.f;
        if (idx < e) {
            int2 ev = d_edge[idx];
            c = ev.x;
            v = __int_as_float(ev.y);
        }
        int cnt = e - base; if (cnt > 32) cnt = 32;
        #pragma unroll 2
        for (int j = 0; j < cnt; j++) {
            int   cj = __shfl_sync(0xffffffffu, c, j);
            float vj = __shfl_sync(0xffffffffu, v, j);
            uint4 q = Pv[(long)cj * 32 + lane];
            float2 f0 = __half22float2(*reinterpret_cast<__half2*>(&q.x));
            float2 f1 = __half22float2(*reinterpret_cast<__half2*>(&q.y));
            float2 f2 = __half22float2(*reinterpret_cast<__half2*>(&q.z));
            float2 f3 = __half22float2(*reinterpret_cast<__half2*>(&q.w));
            acc[0] = fmaf(vj, f0.x, acc[0]);
            acc[1] = fmaf(vj, f0.y, acc[1]);
            acc[2] = fmaf(vj, f1.x, acc[2]);
            acc[3] = fmaf(vj, f1.y, acc[3]);
            acc[4] = fmaf(vj, f2.x, acc[4]);
            acc[5] = fmaf(vj, f2.y, acc[5]);
            acc[6] = fmaf(vj, f3.x, acc[6]);
            acc[7] = fmaf(vj, f3.y, acc[7]);
        }
    }
    float4 o0 = {fmaxf(acc[0], 0.f), fmaxf(acc[1], 0.f), fmaxf(acc[2], 0.f), fmaxf(acc[3], 0.f)};
    float4 o1 = {fmaxf(acc[4], 0.f), fmaxf(acc[5], 0.f), fmaxf(acc[6], 0.f), fmaxf(acc[7], 0.f)};
    float4* outv = reinterpret_cast<float4*>(out);
    outv[(long)warp * 64 + lane * 2]     = o0;
    outv[(long)warp * 64 + lane * 2 + 1] = o1;
}

// ---------------- launch ----------------
extern "C" void kernel_launch(void* const* d_in, const int* in_sizes, int n_in,
                              void* d_out, int out_size) {
    const float* emb  = (const float*)d_in[0];
    const int*   rows = (const int*)  d_in[1];
    const int*   cols = (const int*)  d_in[2];
    const float* vals = (const float*)d_in[3];
    const float* W    = (const float*)d_in[4];
    float* out = (float*)d_out;

    const int N = in_sizes[0] / EMB;   // 100000
    const int E = in_sizes[1];         // 3200000

    const int nsb = (N + SCAN_BLK - 1) / SCAN_BLK;
    const int nblk = (N + GBM - 1) / GBM;

    // Allow 192KB dynamic smem for the persistent GEMM (attribute set is
    // idempotent, not a stream op, capture-safe).
    cudaFuncSetAttribute(gemm_kernel, cudaFuncAttributeMaxDynamicSharedMemorySize, SM_TOTAL);

    // gemm_kernel stays launch idx 3 so ncu profiles it.
    zero_counts_kernel<<<(N + 256) / 256, 256>>>(N);               // 0
    hist_kernel<<<(E + 511) / 512, 512>>>(rows, E);                // 1
    scan_block_kernel<<<nsb, SCAN_BLK>>>(N);                       // 2
    gemm_kernel<<<152, 1024, SM_TOTAL>>>(emb, W, N, nblk);         // 3  <- profiled
    scan_sums_kernel<<<1, 128>>>(nsb, N);                          // 4
    scan_add_kernel<<<nsb, SCAN_BLK>>>(N);                         // 5
    scatter_kernel<<<(E + 511) / 512, 512>>>(rows, cols, vals, E); // 6
    int warps_per_block = 256 / 32;
    int sgrid = (N + warps_per_block - 1) / warps_per_block;
    spmm_relu_kernel<<<sgrid, 256>>>(out, N);                      // 7
}

// round 8
// speedup vs baseline: 2.9056x; 1.0229x over previous
#include <cuda_runtime.h>
#include <cuda_fp16.h>
#include <cuda_bf16.h>
#include <mma.h>

using namespace nvcuda;

// Problem constants.
#define EMB 256
#define MAX_NODES 100000
#define MAX_EDGES 3200000
#define SCAN_BLK 1024
#define MAX_SCAN_BLOCKS 128

// -------- device scratch (no allocations allowed) --------
__device__ __half d_Ph[MAX_NODES * EMB];  // P = emb @ W in fp16 (51.2 MB)
__device__ int   d_rowptr[MAX_NODES + 1];
__device__ int   d_cursor[MAX_NODES + 1];
__device__ int2  d_edge[MAX_EDGES];       // (col, bitcast(val))
__device__ int   d_blocksums[MAX_SCAN_BLOCKS];
__device__ int   d_blockoffs[MAX_SCAN_BLOCKS];

// ---------------- K0: zero counts ----------------
__global__ void zero_counts_kernel(int n) {
    int i = blockIdx.x * blockDim.x + threadIdx.x;
    if (i <= n) d_cursor[i] = 0;
}

// ---------------- K1: histogram of rows ----------------
__global__ void hist_kernel(const int* __restrict__ rows, int E) {
    int e = blockIdx.x * blockDim.x + threadIdx.x;
    if (e < E) atomicAdd(&d_cursor[rows[e]], 1);
}

// ---------------- scan helpers ----------------
__device__ __forceinline__ int warp_incl_scan(int v, int lane) {
    #pragma unroll
    for (int off = 1; off < 32; off <<= 1) {
        int x = __shfl_up_sync(0xffffffffu, v, off);
        if (lane >= off) v += x;
    }
    return v;
}

__global__ __launch_bounds__(SCAN_BLK) void scan_block_kernel(int n) {
    __shared__ int wsum[SCAN_BLK / 32];
    const int t = threadIdx.x;
    const int lane = t & 31;
    const int warp = t >> 5;
    const int i = blockIdx.x * SCAN_BLK + t;

    int v = (i < n) ? d_cursor[i] : 0;
    int incl = warp_incl_scan(v, lane);
    if (lane == 31) wsum[warp] = incl;
    __syncthreads();
    if (warp == 0) {
        int s = (lane < SCAN_BLK / 32) ? wsum[lane] : 0;
        s = warp_incl_scan(s, lane);
        if (lane < SCAN_BLK / 32) wsum[lane] = s;
    }
    __syncthreads();
    int base = (warp > 0) ? wsum[warp - 1] : 0;
    if (i < n) d_rowptr[i] = base + incl - v;
    if (t == SCAN_BLK - 1) d_blocksums[blockIdx.x] = base + incl;
}

__global__ __launch_bounds__(128) void scan_sums_kernel(int nblocks, int n) {
    __shared__ int wsum[4];
    const int t = threadIdx.x;
    const int lane = t & 31;
    const int warp = t >> 5;
    int v = (t < nblocks) ? d_blocksums[t] : 0;
    int incl = warp_incl_scan(v, lane);
    if (lane == 31) wsum[warp] = incl;
    __syncthreads();
    if (warp == 0) {
        int s = (lane < 4) ? wsum[lane] : 0;
        s = warp_incl_scan(s, lane);
        if (lane < 4) wsum[lane] = s;
    }
    __syncthreads();
    int base = (warp > 0) ? wsum[warp - 1] : 0;
    if (t < nblocks) d_blockoffs[t] = base + incl - v;
    if (t == 127) d_rowptr[n] = wsum[3];
}

__global__ __launch_bounds__(SCAN_BLK) void scan_add_kernel(int n) {
    const int i = blockIdx.x * SCAN_BLK + threadIdx.x;
    if (i < n) {
        int r = d_rowptr[i] + d_blockoffs[blockIdx.x];
        d_rowptr[i] = r;
        d_cursor[i] = r;
    }
}

// ---------------- K3: scatter edges into CSR order ----------------
__global__ void scatter_kernel(const int* __restrict__ rows,
                               const int* __restrict__ cols,
                               const float* __restrict__ vals, int E) {
    int e = blockIdx.x * blockDim.x + threadIdx.x;
    if (e < E) {
        int r = rows[e];
        int p = atomicAdd(&d_cursor[r], 1);
        d_edge[p] = make_int2(cols[e], __float_as_int(vals[e]));
    }
}

// ---------------- K4: persistent HMMA GEMM, W + full A block in smem ------
// 152 CTAs x 1024 threads. W (256x256 fp16) resident; each row-block stages
// the ENTIRE 128x256 A tile, then runs all 16 K-step MMAs with no barriers.
// Epilogue slab overlaps the A region (dead after the MMAs).
#define GBM 128
#define AB_LD 264   // 256 + 8 pad (halfs), 528B row stride (16B aligned)
#define E_LD 20     // 16 + 4 pad (floats), 80B row stride (16B aligned)

#define SM_W_BYTES  (256 * AB_LD * 2)           // 135168
#define SM_A_BYTES  (GBM * AB_LD * 2)           // 67584
#define SM_TOTAL    (SM_W_BYTES + SM_A_BYTES)   // 202752 (~198 KB)

extern __shared__ char gemm_smem[];

__global__ __launch_bounds__(1024, 1) void gemm_kernel(const float* __restrict__ A,
                                                       const float* __restrict__ W,
                                                       int M, int nblk) {
    __half (*sWm)[AB_LD] = reinterpret_cast<__half(*)[AB_LD]>(gemm_smem);
    __half (*sA)[AB_LD]  = reinterpret_cast<__half(*)[AB_LD]>(gemm_smem + SM_W_BYTES);
    float  (*sE)[16][E_LD] = reinterpret_cast<float(*)[16][E_LD]>(gemm_smem + SM_W_BYTES);

    const int tid = threadIdx.x;
    const int warp = tid >> 5;
    const int lane = tid & 31;
    const int warp_m = warp >> 3;   // 0..3 -> m offset 32*warp_m
    const int warp_n = warp & 7;    // 0..7 -> n offset 32*warp_n

    // Convert full W (256x256 fp32) into fp16 smem. 16384 float4, 16/thread.
    #pragma unroll
    for (int i = 0; i < 16; i++) {
        int g = tid + i * 1024;
        int r = g >> 6;            // 64 float4 per row
        int c4 = g & 63;
        float4 b = *reinterpret_cast<const float4*>(&W[r * EMB + c4 * 4]);
        __half2* dst = reinterpret_cast<__half2*>(&sWm[r][c4 * 4]);
        dst[0] = __floats2half2_rn(b.x, b.y);
        dst[1] = __floats2half2_rn(b.z, b.w);
    }

    const int er = lane >> 1;      // epilogue row in 16x16 frag
    const int ec0 = (lane & 1) * 8;

    for (int blk = blockIdx.x; blk < nblk; blk += gridDim.x) {
        const int row0 = blk * GBM;

        __syncthreads();   // previous epilogue (overlapping sA) fully read

        // Stage full A block: 128 x 256 fp32 -> fp16. 8192 float4, 8/thread.
        // Independent loads -> high MLP; latency hidden across 32 warps.
        #pragma unroll
        for (int i = 0; i < 8; i++) {
            int g = tid + i * 1024;
            int r = g >> 6;
            int c4 = g & 63;
            float4 a = {0.f, 0.f, 0.f, 0.f};
            if (row0 + r < M)
                a = *reinterpret_cast<const float4*>(&A[(long)(row0 + r) * EMB + c4 * 4]);
            __half2* dst = reinterpret_cast<__half2*>(&sA[r][c4 * 4]);
            dst[0] = __floats2half2_rn(a.x, a.y);
            dst[1] = __floats2half2_rn(a.z, a.w);
        }

        wmma::fragment<wmma::accumulator, 16, 16, 16, float> acc[2][2];
        #pragma unroll
        for (int i = 0; i < 2; i++)
            #pragma unroll
            for (int j = 0; j < 2; j++) wmma::fill_fragment(acc[i][j], 0.f);

        __syncthreads();   // sA ready

        // All 16 K-steps, zero barriers: W and A are read-only smem.
        #pragma unroll
        for (int ks = 0; ks < 16; ks++) {
            #pragma unroll
            for (int j = 0; j < 2; j++) {
                wmma::fragment<wmma::matrix_b, 16, 16, 16, __half, wmma::row_major> bf;
                wmma::load_matrix_sync(bf, &sWm[ks * 16][warp_n * 32 + j * 16], AB_LD);
                #pragma unroll
                for (int i = 0; i < 2; i++) {
                    wmma::fragment<wmma::matrix_a, 16, 16, 16, __half, wmma::row_major> af;
                    wmma::load_matrix_sync(af, &sA[warp_m * 32 + i * 16][ks * 16], AB_LD);
                    wmma::mma_sync(acc[i][j], af, bf, acc[i][j]);
                }
            }
        }

        __syncthreads();   // all MMAs done reading sA; epilogue may overwrite

        // Per-warp epilogue: bounce each 16x16 frag through private slab.
        #pragma unroll
        for (int i = 0; i < 2; i++) {
            #pragma unroll
            for (int j = 0; j < 2; j++) {
                wmma::store_matrix_sync(&sE[warp][0][0], acc[i][j], E_LD, wmma::mem_row_major);
                __syncwarp();
                int g_r = row0 + warp_m * 32 + i * 16 + er;
                if (g_r < M) {
                    float4 v0 = *reinterpret_cast<const float4*>(&sE[warp][er][ec0]);
                    float4 v1 = *reinterpret_cast<const float4*>(&sE[warp][er][ec0 + 4]);
                    __half2 h[4] = {__floats2half2_rn(v0.x, v0.y), __floats2half2_rn(v0.z, v0.w),
                                    __floats2half2_rn(v1.x, v1.y), __floats2half2_rn(v1.z, v1.w)};
                    *reinterpret_cast<uint4*>(&d_Ph[(long)g_r * EMB + warp_n * 32 + j * 16 + ec0]) =
                        *reinterpret_cast<uint4*>(h);
                }
                __syncwarp();
            }
        }
    }
}

// ---------------- K5: SpMM in fp16-P space + ReLU -> fp32 out ----------------
__global__ __launch_bounds__(256) void spmm_relu_kernel(float* __restrict__ out,
                                                        int nrows) {
    const int warp = blockIdx.x * (blockDim.x >> 5) + (threadIdx.x >> 5);
    if (warp >= nrows) return;
    const int lane = threadIdx.x & 31;
    const int s = d_rowptr[warp];
    const int e = d_rowptr[warp + 1];

    float acc[8];
    #pragma unroll
    for (int i = 0; i < 8; i++) acc[i] = 0.f;

    const uint4* __restrict__ Pv = reinterpret_cast<const uint4*>(d_Ph);

    for (int base = s; base < e; base += 32) {
        int idx = base + lane;
        int c = 0;
        float v = 0.f;
        if (idx < e) {
            int2 ev = d_edge[idx];
            c = ev.x;
            v = __int_as_float(ev.y);
        }
        int cnt = e - base; if (cnt > 32) cnt = 32;
        #pragma unroll 2
        for (int j = 0; j < cnt; j++) {
            int   cj = __shfl_sync(0xffffffffu, c, j);
            float vj = __shfl_sync(0xffffffffu, v, j);
            uint4 q = Pv[(long)cj * 32 + lane];
            float2 f0 = __half22float2(*reinterpret_cast<__half2*>(&q.x));
            float2 f1 = __half22float2(*reinterpret_cast<__half2*>(&q.y));
            float2 f2 = __half22float2(*reinterpret_cast<__half2*>(&q.z));
            float2 f3 = __half22float2(*reinterpret_cast<__half2*>(&q.w));
            acc[0] = fmaf(vj, f0.x, acc[0]);
            acc[1] = fmaf(vj, f0.y, acc[1]);
            acc[2] = fmaf(vj, f1.x, acc[2]);
            acc[3] = fmaf(vj, f1.y, acc[3]);
            acc[4] = fmaf(vj, f2.x, acc[4]);
            acc[5] = fmaf(vj, f2.y, acc[5]);
            acc[6] = fmaf(vj, f3.x, acc[6]);
            acc[7] = fmaf(vj, f3.y, acc[7]);
        }
    }
    float4 o0 = {fmaxf(acc[0], 0.f), fmaxf(acc[1], 0.f), fmaxf(acc[2], 0.f), fmaxf(acc[3], 0.f)};
    float4 o1 = {fmaxf(acc[4], 0.f), fmaxf(acc[5], 0.f), fmaxf(acc[6], 0.f), fmaxf(acc[7], 0.f)};
    float4* outv = reinterpret_cast<float4*>(out);
    outv[(long)warp * 64 + lane * 2]     = o0;
    outv[(long)warp * 64 + lane * 2 + 1] = o1;
}

// ---------------- launch ----------------
extern "C" void kernel_launch(void* const* d_in, const int* in_sizes, int n_in,
                              void* d_out, int out_size) {
    const float* emb  = (const float*)d_in[0];
    const int*   rows = (const int*)  d_in[1];
    const int*   cols = (const int*)  d_in[2];
    const float* vals = (const float*)d_in[3];
    const float* W    = (const float*)d_in[4];
    float* out = (float*)d_out;

    const int N = in_sizes[0] / EMB;   // 100000
    const int E = in_sizes[1];         // 3200000

    const int nsb = (N + SCAN_BLK - 1) / SCAN_BLK;
    const int nblk = (N + GBM - 1) / GBM;

    cudaFuncSetAttribute(gemm_kernel, cudaFuncAttributeMaxDynamicSharedMemorySize, SM_TOTAL);

    // gemm_kernel stays launch idx 3 so ncu profiles it.
    zero_counts_kernel<<<(N + 256) / 256, 256>>>(N);               // 0
    hist_kernel<<<(E + 511) / 512, 512>>>(rows, E);                // 1
    scan_block_kernel<<<nsb, SCAN_BLK>>>(N);                       // 2
    gemm_kernel<<<152, 1024, SM_TOTAL>>>(emb, W, N, nblk);         // 3  <- profiled
    scan_sums_kernel<<<1, 128>>>(nsb, N);                          // 4
    scan_add_kernel<<<nsb, SCAN_BLK>>>(N);                         // 5
    scatter_kernel<<<(E + 511) / 512, 512>>>(rows, cols, vals, E); // 6
    int warps_per_block = 256 / 32;
    int sgrid = (N + warps_per_block - 1) / warps_per_block;
    spmm_relu_kernel<<<sgrid, 256>>>(out, N);                      // 7
}